// round 13
// baseline (speedup 1.0000x reference)
#include <cuda_runtime.h>
#include <cuda_fp16.h>
#include <cstdint>

#define B_TOK 4096
#define D_DIM 1024
#define O_DIM 1024
#define E_EXP 8
#define H_DIM 4096
#define NSLOT (B_TOK * 2)
#define PGRID 304              // persistent CTAs (2/SM on 148- or 152-SM parts)
#define W2_ITEMS 512           // w2 convert work items (65536 elems each)

// ---------------- scratch ----------------
__device__ int   g_counts[E_EXP];
__device__ int   g_off[E_EXP + 1];
__device__ int   g_eidx[NSLOT];
__device__ int   g_epos[NSLOT];
__device__ float g_ew[NSLOT];
__device__ int   g_slot[NSLOT];
__device__ int   g_perm[NSLOT];

__device__ int   g_t1pfx[E_EXP + 1];   // layer-1 tile prefix sums
__device__ int   g_t2pfx[E_EXP + 1];   // layer-2 tile prefix sums
__device__ int   g_tickA, g_tickB, g_tickC;
__device__ int   g_done1[E_EXP];
__device__ int   g_doneW2;

__device__ __half g_xq[(size_t)B_TOK * D_DIM];
__device__ __half g_w1q[(size_t)E_EXP * D_DIM * H_DIM];
__device__ __half g_w2q[(size_t)E_EXP * H_DIM * O_DIM];
__device__ __half g_hq[(size_t)NSLOT * H_DIM];
__device__ float  g_y2[(size_t)NSLOT * O_DIM];

// ---------------- PTX helpers ----------------
__device__ __forceinline__ uint32_t smem_u32(const void* p) {
    uint32_t a;
    asm("{ .reg .u64 t; cvta.to.shared.u64 t, %1; cvt.u32.u64 %0, t; }" : "=r"(a) : "l"(p));
    return a;
}
__device__ __forceinline__ void cpa16(uint32_t dst, const void* src) {
    asm volatile("cp.async.cg.shared.global [%0], [%1], 16;\n" :: "r"(dst), "l"(src));
}
#define CP_COMMIT() asm volatile("cp.async.commit_group;" ::: "memory")
template<int N> __device__ __forceinline__ void cp_wait() {
    asm volatile("cp.async.wait_group %0;" :: "n"(N) : "memory");
}

#define LDSM_X4(r0, r1, r2, r3, a) \
    asm volatile("ldmatrix.sync.aligned.m8n8.x4.shared.b16 {%0,%1,%2,%3}, [%4];" \
                 : "=r"(r0), "=r"(r1), "=r"(r2), "=r"(r3) : "r"(a))
#define LDSM_X4T(r0, r1, r2, r3, a) \
    asm volatile("ldmatrix.sync.aligned.m8n8.x4.trans.shared.b16 {%0,%1,%2,%3}, [%4];" \
                 : "=r"(r0), "=r"(r1), "=r"(r2), "=r"(r3) : "r"(a))

__device__ __forceinline__ void mma_f16(float* c, const uint32_t* a, const uint32_t* b) {
    asm volatile(
        "mma.sync.aligned.m16n8k16.row.col.f32.f16.f16.f32 "
        "{%0,%1,%2,%3}, {%4,%5,%6,%7}, {%8,%9}, {%0,%1,%2,%3};"
        : "+f"(c[0]), "+f"(c[1]), "+f"(c[2]), "+f"(c[3])
        : "r"(a[0]), "r"(a[1]), "r"(a[2]), "r"(a[3]), "r"(b[0]), "r"(b[1]));
}

// ---------------- routing (+ fused x conversion) ----------------
__global__ void zero_all_kernel() {
    int t = threadIdx.x;
    if (t < E_EXP) { g_counts[t] = 0; g_done1[t] = 0; }
    if (t == 0) { g_tickA = 0; g_tickB = 0; g_tickC = 0; g_doneW2 = 0; }
}

__global__ void router_kernel(const float* __restrict__ x,
                              const float* __restrict__ gw,
                              const float* __restrict__ gb) {
    int b = blockIdx.x, tid = threadIdx.x;
    const float* xr = x + (size_t)b * D_DIM;
    {
        float4 v = *(const float4*)(xr + tid * 4);
        size_t o = (size_t)b * D_DIM + tid * 4;
        *(__half2*)(g_xq + o)     = __floats2half2_rn(v.x, v.y);
        *(__half2*)(g_xq + o + 2) = __floats2half2_rn(v.z, v.w);
    }
    int e = tid & 7, ds = tid >> 3;
    float p = 0.f;
    #pragma unroll 4
    for (int d = ds; d < D_DIM; d += 32) p += xr[d] * gw[d * E_EXP + e];
    __shared__ float red[256];
    red[tid] = p;
    __syncthreads();
    #pragma unroll
    for (int s = 128; s >= 8; s >>= 1) {
        if (tid < s) red[tid] += red[tid + s];
        __syncthreads();
    }
    if (tid == 0) {
        float v0 = -1e30f, v1 = -1e30f; int i0 = 0, i1 = 0;
        #pragma unroll
        for (int ee = 0; ee < E_EXP; ee++) {
            float v = red[ee] + gb[ee];
            if (v > v0) { v1 = v0; i1 = i0; v0 = v; i0 = ee; }
            else if (v > v1) { v1 = v; i1 = ee; }
        }
        float ex = expf(v1 - v0), inv = 1.f / (1.f + ex);
        int p0 = atomicAdd(&g_counts[i0], 1);
        int p1 = atomicAdd(&g_counts[i1], 1);
        g_eidx[b*2+0] = i0; g_epos[b*2+0] = p0; g_ew[b*2+0] = inv;
        g_eidx[b*2+1] = i1; g_epos[b*2+1] = p1; g_ew[b*2+1] = ex * inv;
    }
}

__global__ void scan_kernel() {
    if (threadIdx.x == 0) {
        int acc = 0, t1 = 0, t2 = 0;
        #pragma unroll
        for (int e = 0; e < E_EXP; e++) {
            g_off[e] = acc;
            g_t1pfx[e] = t1;
            g_t2pfx[e] = t2;
            int cnt = g_counts[e];
            acc += cnt;
            int mt = (cnt + 127) >> 7;
            t1 += mt * (H_DIM / 128);
            t2 += mt * (O_DIM / 128);
        }
        g_off[E_EXP] = acc;
        g_t1pfx[E_EXP] = t1;
        g_t2pfx[E_EXP] = t2;
    }
}

__global__ void scatter_kernel() {
    int i = blockIdx.x * blockDim.x + threadIdx.x;
    if (i >= NSLOT) return;
    int slot = g_off[g_eidx[i]] + g_epos[i];
    g_slot[i] = slot;
    g_perm[slot] = i >> 1;
}

// ---------------- conversion: fp32 -> fp16 (w1, on side stream) ----------------
__global__ void convert_f16_kernel(const float* __restrict__ src,
                                   __half* __restrict__ oq) {
    size_t i = ((size_t)blockIdx.x * 256 + threadIdx.x) * 4;
    float4 v = *(const float4*)(src + i);
    *(__half2*)(oq + i)     = __floats2half2_rn(v.x, v.y);
    *(__half2*)(oq + i + 2) = __floats2half2_rn(v.z, v.w);
}

// ---------------- GEMM tile (R9-verified body as device function) ----------------
#define STAGES 6
#define STAGE_BYTES 16384
#define STG_B 8192
#define GEMM_SMEM (STAGES * STAGE_BYTES)

template <int MODE>
__device__ void gemm_tile(const __half* __restrict__ Aq_base,
                          const __half* __restrict__ Wq_base,
                          const float* __restrict__ bias,
                          float* __restrict__ yout,
                          int KD, int ND, int e, int m0, int n0) {
    extern __shared__ char dsm[];
    __shared__ int s_arow[128];

    int cnt = g_counts[e];
    int off = g_off[e];
    int tid  = threadIdx.x;
    int wid  = tid >> 5, lane = tid & 31;
    int wm   = (wid >> 2) * 64;
    int wn   = (wid & 3) * 32;
    int g    = lane >> 2, t4 = lane & 3;

    const __half* Wq = Wq_base + (size_t)e * KD * ND;

    if (tid < 128) {
        int r = m0 + tid;
        int src = 0;
        if (r < cnt) src = (MODE == 0) ? g_perm[off + r] : (off + r);
        s_arow[tid] = src;
    }
    __syncthreads();

    uint32_t smb = smem_u32(dsm);
    const int NC = KD >> 5;

    auto load_stage = [&](int c) {
        uint32_t sb = smb + (c % STAGES) * STAGE_BYTES;
        int k0 = c << 5;
        #pragma unroll
        for (int t = 0; t < 2; t++) {
            int cid = tid + t * 256;
            int row = cid >> 2, seg = cid & 3;
            uint32_t so = (uint32_t)(row * 64 + seg * 16) ^ (((uint32_t)row & 7u) << 4);
            cpa16(sb + so, Aq_base + (size_t)s_arow[row] * KD + k0 + seg * 8);
        }
        #pragma unroll
        for (int t = 0; t < 2; t++) {
            int cid = tid + t * 256;
            int k = cid >> 4, nseg = cid & 15;
            uint32_t so = (uint32_t)(k * 256 + nseg * 16) ^ (((uint32_t)k & 7u) << 4);
            cpa16(sb + STG_B + so, Wq + (size_t)(k0 + k) * ND + n0 + nseg * 8);
        }
        CP_COMMIT();
    };

    #pragma unroll
    for (int s = 0; s < 5; s++)
        if (s < NC) load_stage(s);

    float acc[4][4][4];
    #pragma unroll
    for (int i = 0; i < 4; i++)
        #pragma unroll
        for (int j = 0; j < 4; j++)
            #pragma unroll
            for (int q = 0; q < 4; q++) acc[i][j][q] = 0.f;

    for (int c = 0; c < NC; c++) {
        int rem = NC - 1 - c;
        if (rem >= 4)      cp_wait<4>();
        else if (rem == 3) cp_wait<3>();
        else if (rem == 2) cp_wait<2>();
        else if (rem == 1) cp_wait<1>();
        else               cp_wait<0>();
        __syncthreads();
        if (c + 5 < NC) load_stage(c + 5);

        uint32_t sb = smb + (c % STAGES) * STAGE_BYTES;

        #pragma unroll
        for (int ks = 0; ks < 2; ks++) {
            uint32_t bq[8];
            int kk = ks * 16 + (lane & 7) + ((lane >> 3) & 1) * 8;
            #pragma unroll
            for (int nf2 = 0; nf2 < 2; nf2++) {
                int noct = (wid & 3) * 4 + nf2 * 2 + (lane >> 4);
                uint32_t so = (uint32_t)(kk * 256 + noct * 16) ^ (((uint32_t)kk & 7u) << 4);
                LDSM_X4T(bq[nf2*4+0], bq[nf2*4+1], bq[nf2*4+2], bq[nf2*4+3], sb + STG_B + so);
            }
            #pragma unroll
            for (int mf = 0; mf < 4; mf++) {
                int row = wm + mf * 16 + (lane & 7) + ((lane >> 3) & 1) * 8;
                int seg = ks * 2 + ((lane >> 4) & 1);
                uint32_t so = (uint32_t)(row * 64 + seg * 16) ^ (((uint32_t)row & 7u) << 4);
                uint32_t aq[4];
                LDSM_X4(aq[0], aq[1], aq[2], aq[3], sb + so);
                #pragma unroll
                for (int nf = 0; nf < 4; nf++)
                    mma_f16(acc[mf][nf], aq, &bq[nf*2]);
            }
        }
    }

    float bias0[4], bias1[4];
    #pragma unroll
    for (int nf = 0; nf < 4; nf++) {
        int n = n0 + wn + nf * 8 + t4 * 2;
        bias0[nf] = bias[e * ND + n];
        bias1[nf] = bias[e * ND + n + 1];
    }

    #pragma unroll
    for (int mf = 0; mf < 4; mf++) {
        #pragma unroll
        for (int half = 0; half < 2; half++) {
            int r = m0 + wm + mf * 16 + g + half * 8;
            if (r >= cnt) continue;
            size_t rb = (size_t)(off + r) * ND + n0 + wn + t4 * 2;
            if (MODE == 0) {
                #pragma unroll
                for (int nf = 0; nf < 4; nf++) {
                    float v0 = acc[mf][nf][half*2+0] + bias0[nf];
                    float v1 = acc[mf][nf][half*2+1] + bias1[nf];
                    v0 = v0 > 0.f ? v0 : 0.f;
                    v1 = v1 > 0.f ? v1 : 0.f;
                    *(__half2*)(g_hq + rb + nf * 8) = __floats2half2_rn(v0, v1);
                }
            } else {
                #pragma unroll
                for (int nf = 0; nf < 4; nf++) {
                    float2 v;
                    v.x = acc[mf][nf][half*2+0] + bias0[nf];
                    v.y = acc[mf][nf][half*2+1] + bias1[nf];
                    *(float2*)(yout + rb + nf * 8) = v;
                }
            }
        }
    }
}

// ---------------- persistent scheduler kernel ----------------
__global__ __launch_bounds__(256, 2)
void moe_persistent(const float* __restrict__ w2src,
                    const float* __restrict__ b1,
                    const float* __restrict__ b2) {
    __shared__ int s_t1pfx[E_EXP + 1], s_t2pfx[E_EXP + 1];
    __shared__ int s_tile;
    int tid = threadIdx.x;
    if (tid <= E_EXP) { s_t1pfx[tid] = g_t1pfx[tid]; s_t2pfx[tid] = g_t2pfx[tid]; }
    __syncthreads();

    // ---- Phase A: layer-1 tiles (pull queue) ----
    for (;;) {
        if (tid == 0) s_tile = atomicAdd(&g_tickA, 1);
        __syncthreads();
        int t = s_tile;
        if (t >= s_t1pfx[E_EXP]) break;
        int e = 0;
        while (t >= s_t1pfx[e + 1]) e++;
        int lt = t - s_t1pfx[e];
        gemm_tile<0>(g_xq, g_w1q, b1, nullptr, D_DIM, H_DIM,
                     e, (lt >> 5) * 128, (lt & 31) * 128);
        __threadfence();
        __syncthreads();
        if (tid == 0) atomicAdd(&g_done1[e], 1);
    }

    // ---- Phase B: w2 conversion (backfills the phase-A tail) ----
    for (;;) {
        if (tid == 0) s_tile = atomicAdd(&g_tickB, 1);
        __syncthreads();
        int t = s_tile;
        if (t >= W2_ITEMS) break;
        size_t base = (size_t)t * 65536;
        #pragma unroll 4
        for (int it = 0; it < 64; it++) {
            size_t i = base + (size_t)it * 1024 + tid * 4;
            float4 v = *(const float4*)(w2src + i);
            *(__half2*)(g_w2q + i)     = __floats2half2_rn(v.x, v.y);
            *(__half2*)(g_w2q + i + 2) = __floats2half2_rn(v.z, v.w);
        }
        __threadfence();
        __syncthreads();
        if (tid == 0) atomicAdd(&g_doneW2, 1);
    }

    // ---- Phase C: layer-2 tiles (spin per expert; deadlock-free: pulled work) ----
    for (;;) {
        if (tid == 0) s_tile = atomicAdd(&g_tickC, 1);
        __syncthreads();
        int t = s_tile;
        if (t >= s_t2pfx[E_EXP]) break;
        int e = 0;
        while (t >= s_t2pfx[e + 1]) e++;
        int lt = t - s_t2pfx[e];
        int need1 = s_t1pfx[e + 1] - s_t1pfx[e];
        if (tid == 0) {
            volatile int* d1 = (volatile int*)&g_done1[e];
            volatile int* dw = (volatile int*)&g_doneW2;
            while (*d1 < need1 || *dw < W2_ITEMS) __nanosleep(128);
            __threadfence();
        }
        __syncthreads();
        gemm_tile<1>(g_hq, g_w2q, b2, g_y2, H_DIM, O_DIM,
                     e, (lt >> 3) * 128, (lt & 7) * 128);
        __syncthreads();
    }
}

// ---------------- combine: y[b] = w0*y2[slot0] + w1*y2[slot1] ----------------
__global__ void combine_kernel(float* __restrict__ y) {
    int b = blockIdx.x, t = threadIdx.x;
    int s0 = g_slot[b*2+0], s1 = g_slot[b*2+1];
    float w0 = g_ew[b*2+0], w1 = g_ew[b*2+1];
    float4 a = *(const float4*)(g_y2 + (size_t)s0 * O_DIM + t * 4);
    float4 c = *(const float4*)(g_y2 + (size_t)s1 * O_DIM + t * 4);
    float4 o;
    o.x = w0 * a.x + w1 * c.x;
    o.y = w0 * a.y + w1 * c.y;
    o.z = w0 * a.z + w1 * c.z;
    o.w = w0 * a.w + w1 * c.w;
    *(float4*)(y + (size_t)b * O_DIM + t * 4) = o;
}

// ---------------- launch ----------------
extern "C" void kernel_launch(void* const* d_in, const int* in_sizes, int n_in,
                              void* d_out, int out_size) {
    const float* x  = (const float*)d_in[0];
    const float* gw = (const float*)d_in[1];
    const float* gb = (const float*)d_in[2];
    const float* w1 = (const float*)d_in[3];
    const float* b1 = (const float*)d_in[4];
    const float* w2 = (const float*)d_in[5];
    const float* b2 = (const float*)d_in[6];
    float* y = (float*)d_out;

    cudaFuncSetAttribute(moe_persistent, cudaFuncAttributeMaxDynamicSharedMemorySize, GEMM_SMEM);

    __half* w1q;
    cudaGetSymbolAddress((void**)&w1q, g_w1q);

    // single side stream (R11-proven guard-safe pattern)
    cudaStream_t s2;
    cudaStreamCreateWithFlags(&s2, cudaStreamNonBlocking);
    cudaEvent_t evFork, evW1;
    cudaEventCreateWithFlags(&evFork, cudaEventDisableTiming);
    cudaEventCreateWithFlags(&evW1,   cudaEventDisableTiming);

    zero_all_kernel<<<1, 32>>>();
    cudaEventRecord(evFork, 0);
    cudaStreamWaitEvent(s2, evFork, 0);

    // side stream: w1 conversion only (w2 converts inside the persistent kernel)
    convert_f16_kernel<<<(E_EXP * D_DIM * H_DIM) / 1024, 256, 0, s2>>>(w1, w1q);
    cudaEventRecord(evW1, s2);

    // main stream: routing chain (x conversion fused into router)
    router_kernel<<<B_TOK, 256>>>(x, gw, gb);
    scan_kernel<<<1, 32>>>();
    scatter_kernel<<<(NSLOT + 255) / 256, 256>>>();

    cudaStreamWaitEvent(0, evW1, 0);
    moe_persistent<<<PGRID, 256, GEMM_SMEM>>>(w2, b1, b2);
    combine_kernel<<<B_TOK, 256>>>(y);
    // stream/events intentionally not destroyed (two invocations only:
    // correctness run + graph capture).
}

// round 14
// speedup vs baseline: 1.2727x; 1.2727x over previous
#include <cuda_runtime.h>
#include <cuda_fp16.h>
#include <cstdint>

#define B_TOK 4096
#define D_DIM 1024
#define O_DIM 1024
#define E_EXP 8
#define H_DIM 4096
#define NSLOT (B_TOK * 2)

// ---------------- scratch ----------------
__device__ int   g_counts[E_EXP];
__device__ int   g_off[E_EXP + 1];
__device__ int   g_eidx[NSLOT];
__device__ int   g_epos[NSLOT];
__device__ float g_ew[NSLOT];
__device__ int   g_slot[NSLOT];
__device__ int   g_perm[NSLOT];

__device__ __half g_xq[(size_t)B_TOK * D_DIM];
__device__ __half g_w1q[(size_t)E_EXP * D_DIM * H_DIM];
__device__ __half g_w2q[(size_t)E_EXP * H_DIM * O_DIM];
__device__ __half g_hq[(size_t)NSLOT * H_DIM];
__device__ float  g_y2[(size_t)NSLOT * O_DIM];

// ---------------- PTX helpers ----------------
__device__ __forceinline__ uint32_t smem_u32(const void* p) {
    uint32_t a;
    asm("{ .reg .u64 t; cvta.to.shared.u64 t, %1; cvt.u32.u64 %0, t; }" : "=r"(a) : "l"(p));
    return a;
}
__device__ __forceinline__ void cpa16(uint32_t dst, const void* src) {
    asm volatile("cp.async.cg.shared.global [%0], [%1], 16;\n" :: "r"(dst), "l"(src));
}
#define CP_COMMIT() asm volatile("cp.async.commit_group;" ::: "memory")
template<int N> __device__ __forceinline__ void cp_wait() {
    asm volatile("cp.async.wait_group %0;" :: "n"(N) : "memory");
}

#define LDSM_X4(r0, r1, r2, r3, a) \
    asm volatile("ldmatrix.sync.aligned.m8n8.x4.shared.b16 {%0,%1,%2,%3}, [%4];" \
                 : "=r"(r0), "=r"(r1), "=r"(r2), "=r"(r3) : "r"(a))
#define LDSM_X4T(r0, r1, r2, r3, a) \
    asm volatile("ldmatrix.sync.aligned.m8n8.x4.trans.shared.b16 {%0,%1,%2,%3}, [%4];" \
                 : "=r"(r0), "=r"(r1), "=r"(r2), "=r"(r3) : "r"(a))

__device__ __forceinline__ void mma_f16(float* c, const uint32_t* a, const uint32_t* b) {
    asm volatile(
        "mma.sync.aligned.m16n8k16.row.col.f32.f16.f16.f32 "
        "{%0,%1,%2,%3}, {%4,%5,%6,%7}, {%8,%9}, {%0,%1,%2,%3};"
        : "+f"(c[0]), "+f"(c[1]), "+f"(c[2]), "+f"(c[3])
        : "r"(a[0]), "r"(a[1]), "r"(a[2]), "r"(a[3]), "r"(b[0]), "r"(b[1]));
}

// ---------------- routing (+ fused x conversion) ----------------
__global__ void zero_counts_kernel() {
    if (threadIdx.x < E_EXP) g_counts[threadIdx.x] = 0;
}

__global__ void router_kernel(const float* __restrict__ x,
                              const float* __restrict__ gw,
                              const float* __restrict__ gb) {
    int b = blockIdx.x, tid = threadIdx.x;
    const float* xr = x + (size_t)b * D_DIM;
    {
        float4 v = *(const float4*)(xr + tid * 4);
        size_t o = (size_t)b * D_DIM + tid * 4;
        *(__half2*)(g_xq + o)     = __floats2half2_rn(v.x, v.y);
        *(__half2*)(g_xq + o + 2) = __floats2half2_rn(v.z, v.w);
    }
    int e = tid & 7, ds = tid >> 3;
    float p = 0.f;
    #pragma unroll 4
    for (int d = ds; d < D_DIM; d += 32) p += xr[d] * gw[d * E_EXP + e];
    __shared__ float red[256];
    red[tid] = p;
    __syncthreads();
    #pragma unroll
    for (int s = 128; s >= 8; s >>= 1) {
        if (tid < s) red[tid] += red[tid + s];
        __syncthreads();
    }
    if (tid == 0) {
        float v0 = -1e30f, v1 = -1e30f; int i0 = 0, i1 = 0;
        #pragma unroll
        for (int ee = 0; ee < E_EXP; ee++) {
            float v = red[ee] + gb[ee];
            if (v > v0) { v1 = v0; i1 = i0; v0 = v; i0 = ee; }
            else if (v > v1) { v1 = v; i1 = ee; }
        }
        float ex = expf(v1 - v0), inv = 1.f / (1.f + ex);
        int p0 = atomicAdd(&g_counts[i0], 1);
        int p1 = atomicAdd(&g_counts[i1], 1);
        g_eidx[b*2+0] = i0; g_epos[b*2+0] = p0; g_ew[b*2+0] = inv;
        g_eidx[b*2+1] = i1; g_epos[b*2+1] = p1; g_ew[b*2+1] = ex * inv;
    }
}

__global__ void scan_kernel() {
    if (threadIdx.x == 0) {
        int acc = 0;
        #pragma unroll
        for (int e = 0; e < E_EXP; e++) { g_off[e] = acc; acc += g_counts[e]; }
        g_off[E_EXP] = acc;
    }
}

__global__ void scatter_kernel() {
    int i = blockIdx.x * blockDim.x + threadIdx.x;
    if (i >= NSLOT) return;
    int slot = g_off[g_eidx[i]] + g_epos[i];
    g_slot[i] = slot;
    g_perm[slot] = i >> 1;
}

// ---------------- conversion: fp32 -> fp16 (weights) ----------------
__global__ void convert_f16_kernel(const float* __restrict__ src,
                                   __half* __restrict__ oq) {
    size_t i = ((size_t)blockIdx.x * 256 + threadIdx.x) * 4;
    float4 v = *(const float4*)(src + i);
    *(__half2*)(oq + i)     = __floats2half2_rn(v.x, v.y);
    *(__half2*)(oq + i + 2) = __floats2half2_rn(v.z, v.w);
}

// ---------------- HMMA grouped GEMM (fp16, single pass) — R9 verified ----------------
// CTA 128x128xBK32, 8 warps 2x4, warp tile 64x32, m16n8k16 f16.
// Stage: A 8K | B 8K = 16KB; 6 stages = 96KB -> 2 CTAs/SM, 5-deep in flight.
// Expert-group launch: e = e_base + blockIdx.z (gridDim.z = group size).
#define STAGES 6
#define STAGE_BYTES 16384
#define STG_B 8192
#define GEMM_SMEM (STAGES * STAGE_BYTES)

template <int MODE>
__global__ __launch_bounds__(256, 2)
void moe_gemm_hmma(const __half* __restrict__ Aq_base,
                   const __half* __restrict__ Wq_base,
                   const float* __restrict__ bias,
                   float* __restrict__ yout,
                   int KD, int ND, int e_base) {
    int e   = e_base + blockIdx.z;
    int cnt = g_counts[e];
    int m0  = blockIdx.y * 128;
    if (m0 >= cnt) return;
    int off = g_off[e];
    int n0  = blockIdx.x * 128;

    extern __shared__ char dsm[];
    __shared__ int s_arow[128];

    int tid  = threadIdx.x;
    int wid  = tid >> 5, lane = tid & 31;
    int wm   = (wid >> 2) * 64;
    int wn   = (wid & 3) * 32;
    int g    = lane >> 2, t4 = lane & 3;

    const __half* Wq = Wq_base + (size_t)e * KD * ND;

    if (tid < 128) {
        int r = m0 + tid;
        int src = 0;
        if (r < cnt) src = (MODE == 0) ? g_perm[off + r] : (off + r);
        s_arow[tid] = src;
    }
    __syncthreads();

    uint32_t smb = smem_u32(dsm);
    const int NC = KD >> 5;

    auto load_stage = [&](int c) {
        uint32_t sb = smb + (c % STAGES) * STAGE_BYTES;
        int k0 = c << 5;
        #pragma unroll
        for (int t = 0; t < 2; t++) {
            int cid = tid + t * 256;
            int row = cid >> 2, seg = cid & 3;
            uint32_t so = (uint32_t)(row * 64 + seg * 16) ^ (((uint32_t)row & 7u) << 4);
            cpa16(sb + so, Aq_base + (size_t)s_arow[row] * KD + k0 + seg * 8);
        }
        #pragma unroll
        for (int t = 0; t < 2; t++) {
            int cid = tid + t * 256;
            int k = cid >> 4, nseg = cid & 15;
            uint32_t so = (uint32_t)(k * 256 + nseg * 16) ^ (((uint32_t)k & 7u) << 4);
            cpa16(sb + STG_B + so, Wq + (size_t)(k0 + k) * ND + n0 + nseg * 8);
        }
        CP_COMMIT();
    };

    #pragma unroll
    for (int s = 0; s < 5; s++)
        if (s < NC) load_stage(s);

    float acc[4][4][4];
    #pragma unroll
    for (int i = 0; i < 4; i++)
        #pragma unroll
        for (int j = 0; j < 4; j++)
            #pragma unroll
            for (int q = 0; q < 4; q++) acc[i][j][q] = 0.f;

    for (int c = 0; c < NC; c++) {
        int rem = NC - 1 - c;
        if (rem >= 4)      cp_wait<4>();
        else if (rem == 3) cp_wait<3>();
        else if (rem == 2) cp_wait<2>();
        else if (rem == 1) cp_wait<1>();
        else               cp_wait<0>();
        __syncthreads();
        if (c + 5 < NC) load_stage(c + 5);

        uint32_t sb = smb + (c % STAGES) * STAGE_BYTES;

        #pragma unroll
        for (int ks = 0; ks < 2; ks++) {
            uint32_t bq[8];
            int kk = ks * 16 + (lane & 7) + ((lane >> 3) & 1) * 8;
            #pragma unroll
            for (int nf2 = 0; nf2 < 2; nf2++) {
                int noct = (wid & 3) * 4 + nf2 * 2 + (lane >> 4);
                uint32_t so = (uint32_t)(kk * 256 + noct * 16) ^ (((uint32_t)kk & 7u) << 4);
                LDSM_X4T(bq[nf2*4+0], bq[nf2*4+1], bq[nf2*4+2], bq[nf2*4+3], sb + STG_B + so);
            }
            #pragma unroll
            for (int mf = 0; mf < 4; mf++) {
                int row = wm + mf * 16 + (lane & 7) + ((lane >> 3) & 1) * 8;
                int seg = ks * 2 + ((lane >> 4) & 1);
                uint32_t so = (uint32_t)(row * 64 + seg * 16) ^ (((uint32_t)row & 7u) << 4);
                uint32_t aq[4];
                LDSM_X4(aq[0], aq[1], aq[2], aq[3], sb + so);
                #pragma unroll
                for (int nf = 0; nf < 4; nf++)
                    mma_f16(acc[mf][nf], aq, &bq[nf*2]);
            }
        }
    }

    // ---------------- epilogue (no atomics) ----------------
    float bias0[4], bias1[4];
    #pragma unroll
    for (int nf = 0; nf < 4; nf++) {
        int n = n0 + wn + nf * 8 + t4 * 2;
        bias0[nf] = bias[e * ND + n];
        bias1[nf] = bias[e * ND + n + 1];
    }

    #pragma unroll
    for (int mf = 0; mf < 4; mf++) {
        #pragma unroll
        for (int half = 0; half < 2; half++) {
            int r = m0 + wm + mf * 16 + g + half * 8;
            if (r >= cnt) continue;
            size_t rb = (size_t)(off + r) * ND + n0 + wn + t4 * 2;
            if (MODE == 0) {
                #pragma unroll
                for (int nf = 0; nf < 4; nf++) {
                    float v0 = acc[mf][nf][half*2+0] + bias0[nf];
                    float v1 = acc[mf][nf][half*2+1] + bias1[nf];
                    v0 = v0 > 0.f ? v0 : 0.f;
                    v1 = v1 > 0.f ? v1 : 0.f;
                    *(__half2*)(g_hq + rb + nf * 8) = __floats2half2_rn(v0, v1);
                }
            } else {
                #pragma unroll
                for (int nf = 0; nf < 4; nf++) {
                    float2 v;
                    v.x = acc[mf][nf][half*2+0] + bias0[nf];
                    v.y = acc[mf][nf][half*2+1] + bias1[nf];
                    *(float2*)(yout + rb + nf * 8) = v;
                }
            }
        }
    }
}

// ---------------- combine: y[b] = w0*y2[slot0] + w1*y2[slot1] ----------------
__global__ void combine_kernel(float* __restrict__ y) {
    int b = blockIdx.x, t = threadIdx.x;
    int s0 = g_slot[b*2+0], s1 = g_slot[b*2+1];
    float w0 = g_ew[b*2+0], w1 = g_ew[b*2+1];
    float4 a = *(const float4*)(g_y2 + (size_t)s0 * O_DIM + t * 4);
    float4 c = *(const float4*)(g_y2 + (size_t)s1 * O_DIM + t * 4);
    float4 o;
    o.x = w0 * a.x + w1 * c.x;
    o.y = w0 * a.y + w1 * c.y;
    o.z = w0 * a.z + w1 * c.z;
    o.w = w0 * a.w + w1 * c.w;
    *(float4*)(y + (size_t)b * O_DIM + t * 4) = o;
}

// ---------------- launch (two expert-group chains on 2 streams) ----------------
extern "C" void kernel_launch(void* const* d_in, const int* in_sizes, int n_in,
                              void* d_out, int out_size) {
    const float* x  = (const float*)d_in[0];
    const float* gw = (const float*)d_in[1];
    const float* gb = (const float*)d_in[2];
    const float* w1 = (const float*)d_in[3];
    const float* b1 = (const float*)d_in[4];
    const float* w2 = (const float*)d_in[5];
    const float* b2 = (const float*)d_in[6];
    float* y = (float*)d_out;

    cudaFuncSetAttribute(moe_gemm_hmma<0>, cudaFuncAttributeMaxDynamicSharedMemorySize, GEMM_SMEM);
    cudaFuncSetAttribute(moe_gemm_hmma<1>, cudaFuncAttributeMaxDynamicSharedMemorySize, GEMM_SMEM);

    __half *xq, *w1q, *w2q, *hq;
    float* y2;
    cudaGetSymbolAddress((void**)&xq,  g_xq);
    cudaGetSymbolAddress((void**)&w1q, g_w1q);
    cudaGetSymbolAddress((void**)&w2q, g_w2q);
    cudaGetSymbolAddress((void**)&hq,  g_hq);
    cudaGetSymbolAddress((void**)&y2,  g_y2);

    // single side stream (R11-proven guard-safe)
    cudaStream_t s2;
    cudaStreamCreateWithFlags(&s2, cudaStreamNonBlocking);
    cudaEvent_t evFork, evW1, evW2, evRoute, evB;
    cudaEventCreateWithFlags(&evFork,  cudaEventDisableTiming);
    cudaEventCreateWithFlags(&evW1,    cudaEventDisableTiming);
    cudaEventCreateWithFlags(&evW2,    cudaEventDisableTiming);
    cudaEventCreateWithFlags(&evRoute, cudaEventDisableTiming);
    cudaEventCreateWithFlags(&evB,     cudaEventDisableTiming);

    cudaEventRecord(evFork, 0);
    cudaStreamWaitEvent(s2, evFork, 0);

    // side stream: weight converts
    convert_f16_kernel<<<(E_EXP * D_DIM * H_DIM) / 1024, 256, 0, s2>>>(w1, w1q);
    cudaEventRecord(evW1, s2);
    convert_f16_kernel<<<(E_EXP * H_DIM * O_DIM) / 1024, 256, 0, s2>>>(w2, w2q);
    cudaEventRecord(evW2, s2);

    // main stream: routing chain (x conversion fused into router)
    zero_counts_kernel<<<1, 32>>>();
    router_kernel<<<B_TOK, 256>>>(x, gw, gb);
    scan_kernel<<<1, 32>>>();
    scatter_kernel<<<(NSLOT + 255) / 256, 256>>>();
    cudaEventRecord(evRoute, 0);

    // group A (experts 0-3) on stream 0
    cudaStreamWaitEvent(0, evW1, 0);
    moe_gemm_hmma<0><<<dim3(H_DIM / 128, 32, 4), 256, GEMM_SMEM>>>(
        xq, w1q, b1, nullptr, D_DIM, H_DIM, 0);
    cudaStreamWaitEvent(0, evW2, 0);
    moe_gemm_hmma<1><<<dim3(O_DIM / 128, 32, 4), 256, GEMM_SMEM>>>(
        hq, w2q, b2, y2, H_DIM, O_DIM, 0);

    // group B (experts 4-7) on s2 (already ordered after both converts)
    cudaStreamWaitEvent(s2, evRoute, 0);
    moe_gemm_hmma<0><<<dim3(H_DIM / 128, 32, 4), 256, GEMM_SMEM, s2>>>(
        xq, w1q, b1, nullptr, D_DIM, H_DIM, 4);
    moe_gemm_hmma<1><<<dim3(O_DIM / 128, 32, 4), 256, GEMM_SMEM, s2>>>(
        hq, w2q, b2, y2, H_DIM, O_DIM, 4);
    cudaEventRecord(evB, s2);

    // join and combine
    cudaStreamWaitEvent(0, evB, 0);
    combine_kernel<<<B_TOK, 256>>>(y);
    // stream/events intentionally not destroyed (two invocations only:
    // correctness run + graph capture).
}

// round 15
// speedup vs baseline: 1.3007x; 1.0220x over previous
#include <cuda_runtime.h>
#include <cuda_fp16.h>
#include <cstdint>

#define B_TOK 4096
#define D_DIM 1024
#define O_DIM 1024
#define E_EXP 8
#define H_DIM 4096
#define NSLOT (B_TOK * 2)

// ---------------- scratch ----------------
__device__ int   g_counts[E_EXP];
__device__ int   g_off[E_EXP + 1];
__device__ int   g_eidx[NSLOT];
__device__ int   g_epos[NSLOT];
__device__ float g_ew[NSLOT];
__device__ int   g_slot[NSLOT];
__device__ int   g_perm[NSLOT];
__device__ volatile int g_scan_flag;

__device__ __half g_xq[(size_t)B_TOK * D_DIM];
__device__ __half g_w1q[(size_t)E_EXP * D_DIM * H_DIM];
__device__ __half g_w2q[(size_t)E_EXP * H_DIM * O_DIM];
__device__ __half g_hq[(size_t)NSLOT * H_DIM];
__device__ float  g_y2[(size_t)NSLOT * O_DIM];

// ---------------- PTX helpers ----------------
__device__ __forceinline__ uint32_t smem_u32(const void* p) {
    uint32_t a;
    asm("{ .reg .u64 t; cvta.to.shared.u64 t, %1; cvt.u32.u64 %0, t; }" : "=r"(a) : "l"(p));
    return a;
}
__device__ __forceinline__ void cpa16(uint32_t dst, const void* src) {
    asm volatile("cp.async.cg.shared.global [%0], [%1], 16;\n" :: "r"(dst), "l"(src));
}
#define CP_COMMIT() asm volatile("cp.async.commit_group;" ::: "memory")
template<int N> __device__ __forceinline__ void cp_wait() {
    asm volatile("cp.async.wait_group %0;" :: "n"(N) : "memory");
}

#define LDSM_X4(r0, r1, r2, r3, a) \
    asm volatile("ldmatrix.sync.aligned.m8n8.x4.shared.b16 {%0,%1,%2,%3}, [%4];" \
                 : "=r"(r0), "=r"(r1), "=r"(r2), "=r"(r3) : "r"(a))
#define LDSM_X4T(r0, r1, r2, r3, a) \
    asm volatile("ldmatrix.sync.aligned.m8n8.x4.trans.shared.b16 {%0,%1,%2,%3}, [%4];" \
                 : "=r"(r0), "=r"(r1), "=r"(r2), "=r"(r3) : "r"(a))

__device__ __forceinline__ void mma_f16(float* c, const uint32_t* a, const uint32_t* b) {
    asm volatile(
        "mma.sync.aligned.m16n8k16.row.col.f32.f16.f16.f32 "
        "{%0,%1,%2,%3}, {%4,%5,%6,%7}, {%8,%9}, {%0,%1,%2,%3};"
        : "+f"(c[0]), "+f"(c[1]), "+f"(c[2]), "+f"(c[3])
        : "r"(a[0]), "r"(a[1]), "r"(a[2]), "r"(a[3]), "r"(b[0]), "r"(b[1]));
}

// ---------------- routing (+ fused x conversion) ----------------
__global__ void zero_counts_kernel() {
    if (threadIdx.x < E_EXP) g_counts[threadIdx.x] = 0;
    if (threadIdx.x == 0) g_scan_flag = 0;
}

__global__ void router_kernel(const float* __restrict__ x,
                              const float* __restrict__ gw,
                              const float* __restrict__ gb) {
    int b = blockIdx.x, tid = threadIdx.x;
    const float* xr = x + (size_t)b * D_DIM;
    {
        float4 v = *(const float4*)(xr + tid * 4);
        size_t o = (size_t)b * D_DIM + tid * 4;
        *(__half2*)(g_xq + o)     = __floats2half2_rn(v.x, v.y);
        *(__half2*)(g_xq + o + 2) = __floats2half2_rn(v.z, v.w);
    }
    int e = tid & 7, ds = tid >> 3;
    float p = 0.f;
    #pragma unroll 4
    for (int d = ds; d < D_DIM; d += 32) p += xr[d] * gw[d * E_EXP + e];
    __shared__ float red[256];
    red[tid] = p;
    __syncthreads();
    #pragma unroll
    for (int s = 128; s >= 8; s >>= 1) {
        if (tid < s) red[tid] += red[tid + s];
        __syncthreads();
    }
    if (tid == 0) {
        float v0 = -1e30f, v1 = -1e30f; int i0 = 0, i1 = 0;
        #pragma unroll
        for (int ee = 0; ee < E_EXP; ee++) {
            float v = red[ee] + gb[ee];
            if (v > v0) { v1 = v0; i1 = i0; v0 = v; i0 = ee; }
            else if (v > v1) { v1 = v; i1 = ee; }
        }
        float ex = expf(v1 - v0), inv = 1.f / (1.f + ex);
        int p0 = atomicAdd(&g_counts[i0], 1);
        int p1 = atomicAdd(&g_counts[i1], 1);
        g_eidx[b*2+0] = i0; g_epos[b*2+0] = p0; g_ew[b*2+0] = inv;
        g_eidx[b*2+1] = i1; g_epos[b*2+1] = p1; g_ew[b*2+1] = ex * inv;
    }
}

// fused scan + scatter: block 0 publishes the 8-entry scan, all 32 blocks spin
// on the flag (all blocks resident on 148 SMs -> no deadlock), then scatter.
__global__ void scan_scatter_kernel() {
    int tid = threadIdx.x;
    if (blockIdx.x == 0 && tid == 0) {
        int acc = 0;
        #pragma unroll
        for (int e = 0; e < E_EXP; e++) { g_off[e] = acc; acc += g_counts[e]; }
        g_off[E_EXP] = acc;
        __threadfence();
        g_scan_flag = 1;
    }
    if (tid == 0) {
        while (g_scan_flag == 0) __nanosleep(64);
        __threadfence();
    }
    __syncthreads();
    int i = blockIdx.x * blockDim.x + tid;
    if (i >= NSLOT) return;
    int slot = g_off[g_eidx[i]] + g_epos[i];
    g_slot[i] = slot;
    g_perm[slot] = i >> 1;
}

// ---------------- conversion: fp32 -> fp16 (weights) ----------------
__global__ void convert_f16_kernel(const float* __restrict__ src,
                                   __half* __restrict__ oq) {
    size_t i = ((size_t)blockIdx.x * 256 + threadIdx.x) * 4;
    float4 v = *(const float4*)(src + i);
    *(__half2*)(oq + i)     = __floats2half2_rn(v.x, v.y);
    *(__half2*)(oq + i + 2) = __floats2half2_rn(v.z, v.w);
}

// ---------------- HMMA grouped GEMM (fp16, single pass, BK=64) ----------------
// CTA 128x128xBK64, 8 warps 2x4, warp tile 64x32, m16n8k16 f16.
// Stage: A 16K | B 16K = 32KB; 3 stages = 96KB -> 2 CTAs/SM, 2-deep in flight.
// Expert-group launch: e = e_base + blockIdx.z.
#define STAGES 3
#define STAGE_BYTES 32768
#define STG_B 16384
#define GEMM_SMEM (STAGES * STAGE_BYTES)

template <int MODE>
__global__ __launch_bounds__(256, 2)
void moe_gemm_hmma(const __half* __restrict__ Aq_base,
                   const __half* __restrict__ Wq_base,
                   const float* __restrict__ bias,
                   float* __restrict__ yout,
                   int KD, int ND, int e_base) {
    int e   = e_base + blockIdx.z;
    int cnt = g_counts[e];
    int m0  = blockIdx.y * 128;
    if (m0 >= cnt) return;
    int off = g_off[e];
    int n0  = blockIdx.x * 128;

    extern __shared__ char dsm[];
    __shared__ int s_arow[128];

    int tid  = threadIdx.x;
    int wid  = tid >> 5, lane = tid & 31;
    int wm   = (wid >> 2) * 64;
    int wn   = (wid & 3) * 32;
    int g    = lane >> 2, t4 = lane & 3;

    const __half* Wq = Wq_base + (size_t)e * KD * ND;

    if (tid < 128) {
        int r = m0 + tid;
        int src = 0;
        if (r < cnt) src = (MODE == 0) ? g_perm[off + r] : (off + r);
        s_arow[tid] = src;
    }
    __syncthreads();

    uint32_t smb = smem_u32(dsm);
    const int NC = KD >> 6;   // 64-wide K chunks

    auto load_stage = [&](int c) {
        uint32_t sb = smb + (c % STAGES) * STAGE_BYTES;
        int k0 = c << 6;
        // A: 128 rows x 8 segs of 16B (128B/row), swizzle ^((row&7)<<4)
        #pragma unroll
        for (int t = 0; t < 4; t++) {
            int cid = tid + t * 256;
            int row = cid >> 3, seg = cid & 7;
            uint32_t so = (uint32_t)(row * 128 + seg * 16) ^ (((uint32_t)row & 7u) << 4);
            cpa16(sb + so, Aq_base + (size_t)s_arow[row] * KD + k0 + seg * 8);
        }
        // B: 64 k-rows x 16 segs of 16B (256B/row), swizzle ^((k&7)<<4)
        #pragma unroll
        for (int t = 0; t < 4; t++) {
            int cid = tid + t * 256;
            int k = cid >> 4, nseg = cid & 15;
            uint32_t so = (uint32_t)(k * 256) + ((uint32_t)(nseg * 16) ^ (((uint32_t)k & 7u) << 4));
            cpa16(sb + STG_B + so, Wq + (size_t)(k0 + k) * ND + n0 + nseg * 8);
        }
        CP_COMMIT();
    };

    load_stage(0);
    if (NC > 1) load_stage(1);

    float acc[4][4][4];
    #pragma unroll
    for (int i = 0; i < 4; i++)
        #pragma unroll
        for (int j = 0; j < 4; j++)
            #pragma unroll
            for (int q = 0; q < 4; q++) acc[i][j][q] = 0.f;

    for (int c = 0; c < NC; c++) {
        if (c + 1 < NC) cp_wait<1>(); else cp_wait<0>();
        __syncthreads();
        if (c + 2 < NC) load_stage(c + 2);

        uint32_t sb = smb + (c % STAGES) * STAGE_BYTES;

        #pragma unroll
        for (int ks = 0; ks < 4; ks++) {
            uint32_t bq[8];
            int kk = ks * 16 + (lane & 7) + ((lane >> 3) & 1) * 8;
            #pragma unroll
            for (int nf2 = 0; nf2 < 2; nf2++) {
                int noct = (wid & 3) * 4 + nf2 * 2 + (lane >> 4);
                uint32_t so = (uint32_t)(kk * 256) + ((uint32_t)(noct * 16) ^ (((uint32_t)kk & 7u) << 4));
                LDSM_X4T(bq[nf2*4+0], bq[nf2*4+1], bq[nf2*4+2], bq[nf2*4+3], sb + STG_B + so);
            }
            #pragma unroll
            for (int mf = 0; mf < 4; mf++) {
                int row = wm + mf * 16 + (lane & 7) + ((lane >> 3) & 1) * 8;
                int seg = ks * 2 + ((lane >> 4) & 1);
                uint32_t so = (uint32_t)(row * 128 + seg * 16) ^ (((uint32_t)row & 7u) << 4);
                uint32_t aq[4];
                LDSM_X4(aq[0], aq[1], aq[2], aq[3], sb + so);
                #pragma unroll
                for (int nf = 0; nf < 4; nf++)
                    mma_f16(acc[mf][nf], aq, &bq[nf*2]);
            }
        }
    }

    // ---------------- epilogue (no atomics) ----------------
    float bias0[4], bias1[4];
    #pragma unroll
    for (int nf = 0; nf < 4; nf++) {
        int n = n0 + wn + nf * 8 + t4 * 2;
        bias0[nf] = bias[e * ND + n];
        bias1[nf] = bias[e * ND + n + 1];
    }

    #pragma unroll
    for (int mf = 0; mf < 4; mf++) {
        #pragma unroll
        for (int half = 0; half < 2; half++) {
            int r = m0 + wm + mf * 16 + g + half * 8;
            if (r >= cnt) continue;
            size_t rb = (size_t)(off + r) * ND + n0 + wn + t4 * 2;
            if (MODE == 0) {
                #pragma unroll
                for (int nf = 0; nf < 4; nf++) {
                    float v0 = acc[mf][nf][half*2+0] + bias0[nf];
                    float v1 = acc[mf][nf][half*2+1] + bias1[nf];
                    v0 = v0 > 0.f ? v0 : 0.f;
                    v1 = v1 > 0.f ? v1 : 0.f;
                    *(__half2*)(g_hq + rb + nf * 8) = __floats2half2_rn(v0, v1);
                }
            } else {
                #pragma unroll
                for (int nf = 0; nf < 4; nf++) {
                    float2 v;
                    v.x = acc[mf][nf][half*2+0] + bias0[nf];
                    v.y = acc[mf][nf][half*2+1] + bias1[nf];
                    *(float2*)(yout + rb + nf * 8) = v;
                }
            }
        }
    }
}

// ---------------- combine: y[b] = w0*y2[slot0] + w1*y2[slot1] ----------------
__global__ void combine_kernel(float* __restrict__ y) {
    int b = blockIdx.x, t = threadIdx.x;
    int s0 = g_slot[b*2+0], s1 = g_slot[b*2+1];
    float w0 = g_ew[b*2+0], w1 = g_ew[b*2+1];
    float4 a = *(const float4*)(g_y2 + (size_t)s0 * O_DIM + t * 4);
    float4 c = *(const float4*)(g_y2 + (size_t)s1 * O_DIM + t * 4);
    float4 o;
    o.x = w0 * a.x + w1 * c.x;
    o.y = w0 * a.y + w1 * c.y;
    o.z = w0 * a.z + w1 * c.z;
    o.w = w0 * a.w + w1 * c.w;
    *(float4*)(y + (size_t)b * O_DIM + t * 4) = o;
}

// ---------------- launch (two expert-group chains on 2 streams) ----------------
extern "C" void kernel_launch(void* const* d_in, const int* in_sizes, int n_in,
                              void* d_out, int out_size) {
    const float* x  = (const float*)d_in[0];
    const float* gw = (const float*)d_in[1];
    const float* gb = (const float*)d_in[2];
    const float* w1 = (const float*)d_in[3];
    const float* b1 = (const float*)d_in[4];
    const float* w2 = (const float*)d_in[5];
    const float* b2 = (const float*)d_in[6];
    float* y = (float*)d_out;

    cudaFuncSetAttribute(moe_gemm_hmma<0>, cudaFuncAttributeMaxDynamicSharedMemorySize, GEMM_SMEM);
    cudaFuncSetAttribute(moe_gemm_hmma<1>, cudaFuncAttributeMaxDynamicSharedMemorySize, GEMM_SMEM);

    __half *xq, *w1q, *w2q, *hq;
    float* y2;
    cudaGetSymbolAddress((void**)&xq,  g_xq);
    cudaGetSymbolAddress((void**)&w1q, g_w1q);
    cudaGetSymbolAddress((void**)&w2q, g_w2q);
    cudaGetSymbolAddress((void**)&hq,  g_hq);
    cudaGetSymbolAddress((void**)&y2,  g_y2);

    // single side stream (R11/R14-proven guard-safe)
    cudaStream_t s2;
    cudaStreamCreateWithFlags(&s2, cudaStreamNonBlocking);
    cudaEvent_t evFork, evW1, evW2, evRoute, evB;
    cudaEventCreateWithFlags(&evFork,  cudaEventDisableTiming);
    cudaEventCreateWithFlags(&evW1,    cudaEventDisableTiming);
    cudaEventCreateWithFlags(&evW2,    cudaEventDisableTiming);
    cudaEventCreateWithFlags(&evRoute, cudaEventDisableTiming);
    cudaEventCreateWithFlags(&evB,     cudaEventDisableTiming);

    cudaEventRecord(evFork, 0);
    cudaStreamWaitEvent(s2, evFork, 0);

    // side stream: weight converts
    convert_f16_kernel<<<(E_EXP * D_DIM * H_DIM) / 1024, 256, 0, s2>>>(w1, w1q);
    cudaEventRecord(evW1, s2);
    convert_f16_kernel<<<(E_EXP * H_DIM * O_DIM) / 1024, 256, 0, s2>>>(w2, w2q);
    cudaEventRecord(evW2, s2);

    // main stream: routing chain (x conversion fused into router; scan fused into scatter)
    zero_counts_kernel<<<1, 32>>>();
    router_kernel<<<B_TOK, 256>>>(x, gw, gb);
    scan_scatter_kernel<<<(NSLOT + 255) / 256, 256>>>();
    cudaEventRecord(evRoute, 0);

    // group A (experts 0-3) on stream 0
    cudaStreamWaitEvent(0, evW1, 0);
    moe_gemm_hmma<0><<<dim3(H_DIM / 128, 32, 4), 256, GEMM_SMEM>>>(
        xq, w1q, b1, nullptr, D_DIM, H_DIM, 0);
    cudaStreamWaitEvent(0, evW2, 0);
    moe_gemm_hmma<1><<<dim3(O_DIM / 128, 32, 4), 256, GEMM_SMEM>>>(
        hq, w2q, b2, y2, H_DIM, O_DIM, 0);

    // group B (experts 4-7) on s2 (already ordered after both converts)
    cudaStreamWaitEvent(s2, evRoute, 0);
    moe_gemm_hmma<0><<<dim3(H_DIM / 128, 32, 4), 256, GEMM_SMEM, s2>>>(
        xq, w1q, b1, nullptr, D_DIM, H_DIM, 4);
    moe_gemm_hmma<1><<<dim3(O_DIM / 128, 32, 4), 256, GEMM_SMEM, s2>>>(
        hq, w2q, b2, y2, H_DIM, O_DIM, 4);
    cudaEventRecord(evB, s2);

    // join and combine
    cudaStreamWaitEvent(0, evB, 0);
    combine_kernel<<<B_TOK, 256>>>(y);
    // stream/events intentionally not destroyed (two invocations only:
    // correctness run + graph capture).
}

// round 16
// speedup vs baseline: 1.3025x; 1.0014x over previous
#include <cuda_runtime.h>
#include <cuda_fp16.h>
#include <cstdint>

#define B_TOK 4096
#define D_DIM 1024
#define O_DIM 1024
#define E_EXP 8
#define H_DIM 4096
#define NSLOT (B_TOK * 2)

// ---------------- scratch ----------------
__device__ int   g_counts[E_EXP];
__device__ int   g_off[E_EXP + 1];
__device__ int   g_eidx[NSLOT];
__device__ int   g_epos[NSLOT];
__device__ float g_ew[NSLOT];
__device__ int   g_perm[NSLOT];
__device__ float g_rws[NSLOT];
__device__ volatile int g_scan_flag;

__device__ __half g_xq[(size_t)B_TOK * D_DIM];
__device__ __half g_w1q[(size_t)E_EXP * D_DIM * H_DIM];
__device__ __half g_w2q[(size_t)E_EXP * H_DIM * O_DIM];
__device__ __half g_hq[(size_t)NSLOT * H_DIM];

// ---------------- PTX helpers ----------------
__device__ __forceinline__ uint32_t smem_u32(const void* p) {
    uint32_t a;
    asm("{ .reg .u64 t; cvta.to.shared.u64 t, %1; cvt.u32.u64 %0, t; }" : "=r"(a) : "l"(p));
    return a;
}
__device__ __forceinline__ void cpa16(uint32_t dst, const void* src) {
    asm volatile("cp.async.cg.shared.global [%0], [%1], 16;\n" :: "r"(dst), "l"(src));
}
#define CP_COMMIT() asm volatile("cp.async.commit_group;" ::: "memory")
template<int N> __device__ __forceinline__ void cp_wait() {
    asm volatile("cp.async.wait_group %0;" :: "n"(N) : "memory");
}

#define LDSM_X4(r0, r1, r2, r3, a) \
    asm volatile("ldmatrix.sync.aligned.m8n8.x4.shared.b16 {%0,%1,%2,%3}, [%4];" \
                 : "=r"(r0), "=r"(r1), "=r"(r2), "=r"(r3) : "r"(a))
#define LDSM_X4T(r0, r1, r2, r3, a) \
    asm volatile("ldmatrix.sync.aligned.m8n8.x4.trans.shared.b16 {%0,%1,%2,%3}, [%4];" \
                 : "=r"(r0), "=r"(r1), "=r"(r2), "=r"(r3) : "r"(a))

__device__ __forceinline__ void mma_f16(float* c, const uint32_t* a, const uint32_t* b) {
    asm volatile(
        "mma.sync.aligned.m16n8k16.row.col.f32.f16.f16.f32 "
        "{%0,%1,%2,%3}, {%4,%5,%6,%7}, {%8,%9}, {%0,%1,%2,%3};"
        : "+f"(c[0]), "+f"(c[1]), "+f"(c[2]), "+f"(c[3])
        : "r"(a[0]), "r"(a[1]), "r"(a[2]), "r"(a[3]), "r"(b[0]), "r"(b[1]));
}

// ---------------- routing (+ fused x conversion, shuffle reduction) ----------------
__global__ void zero_counts_kernel() {
    if (threadIdx.x < E_EXP) g_counts[threadIdx.x] = 0;
    if (threadIdx.x == 0) g_scan_flag = 0;
}

__global__ void router_kernel(const float* __restrict__ x,
                              const float* __restrict__ gw,
                              const float* __restrict__ gb) {
    int b = blockIdx.x, tid = threadIdx.x;
    const float* xr = x + (size_t)b * D_DIM;
    {
        float4 v = *(const float4*)(xr + tid * 4);
        size_t o = (size_t)b * D_DIM + tid * 4;
        *(__half2*)(g_xq + o)     = __floats2half2_rn(v.x, v.y);
        *(__half2*)(g_xq + o + 2) = __floats2half2_rn(v.z, v.w);
    }
    int e = tid & 7, ds = tid >> 3;
    float p = 0.f;
    #pragma unroll 4
    for (int d = ds; d < D_DIM; d += 32) p += xr[d] * gw[d * E_EXP + e];

    __shared__ float red[256];
    __shared__ float slog[E_EXP];
    red[tid] = p;
    __syncthreads();
    if (tid < 32) {
        // partials for (e = tid&7) live at indices (tid&7) + 8*ds, ds = 0..31
        float s = 0.f;
        #pragma unroll
        for (int j = 0; j < 8; j++)
            s += red[(tid & 7) + 64 * (tid >> 3) + 8 * j];
        s += __shfl_xor_sync(0xffffffffu, s, 8);
        s += __shfl_xor_sync(0xffffffffu, s, 16);
        if (tid < E_EXP) slog[tid] = s + gb[tid];
    }
    __syncthreads();
    if (tid == 0) {
        float v0 = -1e30f, v1 = -1e30f; int i0 = 0, i1 = 0;
        #pragma unroll
        for (int ee = 0; ee < E_EXP; ee++) {
            float v = slog[ee];
            if (v > v0) { v1 = v0; i1 = i0; v0 = v; i0 = ee; }
            else if (v > v1) { v1 = v; i1 = ee; }
        }
        float ex = expf(v1 - v0), inv = 1.f / (1.f + ex);
        int p0 = atomicAdd(&g_counts[i0], 1);
        int p1 = atomicAdd(&g_counts[i1], 1);
        g_eidx[b*2+0] = i0; g_epos[b*2+0] = p0; g_ew[b*2+0] = inv;
        g_eidx[b*2+1] = i1; g_epos[b*2+1] = p1; g_ew[b*2+1] = ex * inv;
    }
}

// fused scan + scatter: block 0 publishes the 8-entry scan, all 32 blocks spin
// on the flag (all blocks resident -> no deadlock), then scatter.
__global__ void scan_scatter_kernel() {
    int tid = threadIdx.x;
    if (blockIdx.x == 0 && tid == 0) {
        int acc = 0;
        #pragma unroll
        for (int e = 0; e < E_EXP; e++) { g_off[e] = acc; acc += g_counts[e]; }
        g_off[E_EXP] = acc;
        __threadfence();
        g_scan_flag = 1;
    }
    if (tid == 0) {
        while (g_scan_flag == 0) __nanosleep(64);
        __threadfence();
    }
    __syncthreads();
    int i = blockIdx.x * blockDim.x + tid;
    if (i >= NSLOT) return;
    int slot = g_off[g_eidx[i]] + g_epos[i];
    g_perm[slot] = i >> 1;
    g_rws[slot]  = g_ew[i];
}

// ---------------- conversion: fp32 -> fp16 (weights) ----------------
__global__ void convert_f16_kernel(const float* __restrict__ src,
                                   __half* __restrict__ oq) {
    size_t i = ((size_t)blockIdx.x * 256 + threadIdx.x) * 4;
    float4 v = *(const float4*)(src + i);
    *(__half2*)(oq + i)     = __floats2half2_rn(v.x, v.y);
    *(__half2*)(oq + i + 2) = __floats2half2_rn(v.z, v.w);
}

// ---------------- HMMA grouped GEMM (fp16, single pass, BK=64) — R15 core ----------------
// CTA 128x128xBK64, 8 warps 2x4, warp tile 64x32, m16n8k16 f16.
// Stage: A 16K | B 16K = 32KB; 3 stages = 96KB -> 2 CTAs/SM, 2-deep in flight.
// MODE 1 epilogue: atomicAdd rw*(acc+bias) directly into y (combine folded in).
#define STAGES 3
#define STAGE_BYTES 32768
#define STG_B 16384
#define GEMM_SMEM (STAGES * STAGE_BYTES)

template <int MODE>
__global__ __launch_bounds__(256, 2)
void moe_gemm_hmma(const __half* __restrict__ Aq_base,
                   const __half* __restrict__ Wq_base,
                   const float* __restrict__ bias,
                   float* __restrict__ yout,
                   int KD, int ND, int e_base) {
    int e   = e_base + blockIdx.z;
    int cnt = g_counts[e];
    int m0  = blockIdx.y * 128;
    if (m0 >= cnt) return;
    int off = g_off[e];
    int n0  = blockIdx.x * 128;

    extern __shared__ char dsm[];
    __shared__ int s_arow[128];

    int tid  = threadIdx.x;
    int wid  = tid >> 5, lane = tid & 31;
    int wm   = (wid >> 2) * 64;
    int wn   = (wid & 3) * 32;
    int g    = lane >> 2, t4 = lane & 3;

    const __half* Wq = Wq_base + (size_t)e * KD * ND;

    if (tid < 128) {
        int r = m0 + tid;
        int src = 0;
        if (r < cnt) src = (MODE == 0) ? g_perm[off + r] : (off + r);
        s_arow[tid] = src;
    }
    __syncthreads();

    uint32_t smb = smem_u32(dsm);
    const int NC = KD >> 6;

    auto load_stage = [&](int c) {
        uint32_t sb = smb + (c % STAGES) * STAGE_BYTES;
        int k0 = c << 6;
        #pragma unroll
        for (int t = 0; t < 4; t++) {
            int cid = tid + t * 256;
            int row = cid >> 3, seg = cid & 7;
            uint32_t so = (uint32_t)(row * 128 + seg * 16) ^ (((uint32_t)row & 7u) << 4);
            cpa16(sb + so, Aq_base + (size_t)s_arow[row] * KD + k0 + seg * 8);
        }
        #pragma unroll
        for (int t = 0; t < 4; t++) {
            int cid = tid + t * 256;
            int k = cid >> 4, nseg = cid & 15;
            uint32_t so = (uint32_t)(k * 256) + ((uint32_t)(nseg * 16) ^ (((uint32_t)k & 7u) << 4));
            cpa16(sb + STG_B + so, Wq + (size_t)(k0 + k) * ND + n0 + nseg * 8);
        }
        CP_COMMIT();
    };

    load_stage(0);
    if (NC > 1) load_stage(1);

    float acc[4][4][4];
    #pragma unroll
    for (int i = 0; i < 4; i++)
        #pragma unroll
        for (int j = 0; j < 4; j++)
            #pragma unroll
            for (int q = 0; q < 4; q++) acc[i][j][q] = 0.f;

    for (int c = 0; c < NC; c++) {
        if (c + 1 < NC) cp_wait<1>(); else cp_wait<0>();
        __syncthreads();
        if (c + 2 < NC) load_stage(c + 2);

        uint32_t sb = smb + (c % STAGES) * STAGE_BYTES;

        #pragma unroll
        for (int ks = 0; ks < 4; ks++) {
            uint32_t bq[8];
            int kk = ks * 16 + (lane & 7) + ((lane >> 3) & 1) * 8;
            #pragma unroll
            for (int nf2 = 0; nf2 < 2; nf2++) {
                int noct = (wid & 3) * 4 + nf2 * 2 + (lane >> 4);
                uint32_t so = (uint32_t)(kk * 256) + ((uint32_t)(noct * 16) ^ (((uint32_t)kk & 7u) << 4));
                LDSM_X4T(bq[nf2*4+0], bq[nf2*4+1], bq[nf2*4+2], bq[nf2*4+3], sb + STG_B + so);
            }
            #pragma unroll
            for (int mf = 0; mf < 4; mf++) {
                int row = wm + mf * 16 + (lane & 7) + ((lane >> 3) & 1) * 8;
                int seg = ks * 2 + ((lane >> 4) & 1);
                uint32_t so = (uint32_t)(row * 128 + seg * 16) ^ (((uint32_t)row & 7u) << 4);
                uint32_t aq[4];
                LDSM_X4(aq[0], aq[1], aq[2], aq[3], sb + so);
                #pragma unroll
                for (int nf = 0; nf < 4; nf++)
                    mma_f16(acc[mf][nf], aq, &bq[nf*2]);
            }
        }
    }

    // ---------------- epilogue ----------------
    float bias0[4], bias1[4];
    #pragma unroll
    for (int nf = 0; nf < 4; nf++) {
        int n = n0 + wn + nf * 8 + t4 * 2;
        bias0[nf] = bias[e * ND + n];
        bias1[nf] = bias[e * ND + n + 1];
    }

    #pragma unroll
    for (int mf = 0; mf < 4; mf++) {
        #pragma unroll
        for (int half = 0; half < 2; half++) {
            int r = m0 + wm + mf * 16 + g + half * 8;
            if (r >= cnt) continue;
            if (MODE == 0) {
                size_t rb = (size_t)(off + r) * ND + n0 + wn + t4 * 2;
                #pragma unroll
                for (int nf = 0; nf < 4; nf++) {
                    float v0 = acc[mf][nf][half*2+0] + bias0[nf];
                    float v1 = acc[mf][nf][half*2+1] + bias1[nf];
                    v0 = v0 > 0.f ? v0 : 0.f;
                    v1 = v1 > 0.f ? v1 : 0.f;
                    *(__half2*)(g_hq + rb + nf * 8) = __floats2half2_rn(v0, v1);
                }
            } else {
                int tok  = g_perm[off + r];
                float rw = g_rws[off + r];
                float* orow = yout + (size_t)tok * ND + n0 + wn + t4 * 2;
                #pragma unroll
                for (int nf = 0; nf < 4; nf++) {
                    atomicAdd(&orow[nf * 8 + 0], rw * (acc[mf][nf][half*2+0] + bias0[nf]));
                    atomicAdd(&orow[nf * 8 + 1], rw * (acc[mf][nf][half*2+1] + bias1[nf]));
                }
            }
        }
    }
}

// ---------------- launch (two expert-group chains on 2 streams) ----------------
extern "C" void kernel_launch(void* const* d_in, const int* in_sizes, int n_in,
                              void* d_out, int out_size) {
    const float* x  = (const float*)d_in[0];
    const float* gw = (const float*)d_in[1];
    const float* gb = (const float*)d_in[2];
    const float* w1 = (const float*)d_in[3];
    const float* b1 = (const float*)d_in[4];
    const float* w2 = (const float*)d_in[5];
    const float* b2 = (const float*)d_in[6];
    float* y = (float*)d_out;

    cudaFuncSetAttribute(moe_gemm_hmma<0>, cudaFuncAttributeMaxDynamicSharedMemorySize, GEMM_SMEM);
    cudaFuncSetAttribute(moe_gemm_hmma<1>, cudaFuncAttributeMaxDynamicSharedMemorySize, GEMM_SMEM);

    __half *xq, *w1q, *w2q, *hq;
    cudaGetSymbolAddress((void**)&xq,  g_xq);
    cudaGetSymbolAddress((void**)&w1q, g_w1q);
    cudaGetSymbolAddress((void**)&w2q, g_w2q);
    cudaGetSymbolAddress((void**)&hq,  g_hq);

    // single side stream (guard-proven pattern)
    cudaStream_t s2;
    cudaStreamCreateWithFlags(&s2, cudaStreamNonBlocking);
    cudaEvent_t evFork, evW1, evW2, evRoute, evB;
    cudaEventCreateWithFlags(&evFork,  cudaEventDisableTiming);
    cudaEventCreateWithFlags(&evW1,    cudaEventDisableTiming);
    cudaEventCreateWithFlags(&evW2,    cudaEventDisableTiming);
    cudaEventCreateWithFlags(&evRoute, cudaEventDisableTiming);
    cudaEventCreateWithFlags(&evB,     cudaEventDisableTiming);

    // y must be zero before layer-2 atomics; ordered before the fork so both
    // streams' GEMM2 launches are transitively after it.
    cudaMemsetAsync(y, 0, (size_t)out_size * sizeof(float));
    zero_counts_kernel<<<1, 32>>>();
    cudaEventRecord(evFork, 0);
    cudaStreamWaitEvent(s2, evFork, 0);

    // side stream: weight converts
    convert_f16_kernel<<<(E_EXP * D_DIM * H_DIM) / 1024, 256, 0, s2>>>(w1, w1q);
    cudaEventRecord(evW1, s2);
    convert_f16_kernel<<<(E_EXP * H_DIM * O_DIM) / 1024, 256, 0, s2>>>(w2, w2q);
    cudaEventRecord(evW2, s2);

    // main stream: routing chain (x convert fused in router; scan fused in scatter)
    router_kernel<<<B_TOK, 256>>>(x, gw, gb);
    scan_scatter_kernel<<<(NSLOT + 255) / 256, 256>>>();
    cudaEventRecord(evRoute, 0);

    // group A (experts 0-3) on stream 0
    cudaStreamWaitEvent(0, evW1, 0);
    moe_gemm_hmma<0><<<dim3(H_DIM / 128, 32, 4), 256, GEMM_SMEM>>>(
        xq, w1q, b1, nullptr, D_DIM, H_DIM, 0);
    cudaStreamWaitEvent(0, evW2, 0);
    moe_gemm_hmma<1><<<dim3(O_DIM / 128, 32, 4), 256, GEMM_SMEM>>>(
        hq, w2q, b2, y, H_DIM, O_DIM, 0);

    // group B (experts 4-7) on s2 (already ordered after both converts)
    cudaStreamWaitEvent(s2, evRoute, 0);
    moe_gemm_hmma<0><<<dim3(H_DIM / 128, 32, 4), 256, GEMM_SMEM, s2>>>(
        xq, w1q, b1, nullptr, D_DIM, H_DIM, 4);
    moe_gemm_hmma<1><<<dim3(O_DIM / 128, 32, 4), 256, GEMM_SMEM, s2>>>(
        hq, w2q, b2, y, H_DIM, O_DIM, 4);
    cudaEventRecord(evB, s2);

    // join side stream back into the capture-origin stream
    cudaStreamWaitEvent(0, evB, 0);
    // stream/events intentionally not destroyed (two invocations only:
    // correctness run + graph capture).
}

// round 17
// speedup vs baseline: 1.3139x; 1.0088x over previous
#include <cuda_runtime.h>
#include <cuda_fp16.h>
#include <cstdint>

#define B_TOK 4096
#define D_DIM 1024
#define O_DIM 1024
#define E_EXP 8
#define H_DIM 4096
#define NSLOT (B_TOK * 2)

// ---------------- scratch ----------------
__device__ int   g_counts[E_EXP];
__device__ int   g_off[E_EXP + 1];
__device__ int   g_eidx[NSLOT];
__device__ int   g_epos[NSLOT];
__device__ float g_ew[NSLOT];
__device__ int   g_perm[NSLOT];
__device__ float g_rws[NSLOT];
__device__ volatile int g_scan_flag;

__device__ __half g_xq[(size_t)B_TOK * D_DIM];
__device__ __half g_w1q[(size_t)E_EXP * D_DIM * H_DIM];
__device__ __half g_w2q[(size_t)E_EXP * H_DIM * O_DIM];
__device__ __half g_hq[(size_t)NSLOT * H_DIM];

// ---------------- PTX helpers ----------------
__device__ __forceinline__ uint32_t smem_u32(const void* p) {
    uint32_t a;
    asm("{ .reg .u64 t; cvta.to.shared.u64 t, %1; cvt.u32.u64 %0, t; }" : "=r"(a) : "l"(p));
    return a;
}
__device__ __forceinline__ void cpa16(uint32_t dst, const void* src) {
    asm volatile("cp.async.cg.shared.global [%0], [%1], 16;\n" :: "r"(dst), "l"(src));
}
#define CP_COMMIT() asm volatile("cp.async.commit_group;" ::: "memory")
template<int N> __device__ __forceinline__ void cp_wait() {
    asm volatile("cp.async.wait_group %0;" :: "n"(N) : "memory");
}

#define LDSM_X4(r0, r1, r2, r3, a) \
    asm volatile("ldmatrix.sync.aligned.m8n8.x4.shared.b16 {%0,%1,%2,%3}, [%4];" \
                 : "=r"(r0), "=r"(r1), "=r"(r2), "=r"(r3) : "r"(a))
#define LDSM_X4T(r0, r1, r2, r3, a) \
    asm volatile("ldmatrix.sync.aligned.m8n8.x4.trans.shared.b16 {%0,%1,%2,%3}, [%4];" \
                 : "=r"(r0), "=r"(r1), "=r"(r2), "=r"(r3) : "r"(a))

__device__ __forceinline__ void mma_f16(float* c, const uint32_t* a, const uint32_t* b) {
    asm volatile(
        "mma.sync.aligned.m16n8k16.row.col.f32.f16.f16.f32 "
        "{%0,%1,%2,%3}, {%4,%5,%6,%7}, {%8,%9}, {%0,%1,%2,%3};"
        : "+f"(c[0]), "+f"(c[1]), "+f"(c[2]), "+f"(c[3])
        : "r"(a[0]), "r"(a[1]), "r"(a[2]), "r"(a[3]), "r"(b[0]), "r"(b[1]));
}

// ---------------- routing: warp-per-token, zero block barriers ----------------
__global__ void zero_counts_kernel() {
    if (threadIdx.x < E_EXP) g_counts[threadIdx.x] = 0;
    if (threadIdx.x == 0) g_scan_flag = 0;
}

__global__ void router_kernel(const float* __restrict__ x,
                              const float* __restrict__ gw,
                              const float* __restrict__ gb) {
    int wid = threadIdx.x >> 5, lane = threadIdx.x & 31;
    int b = blockIdx.x * 8 + wid;
    const float* xr = x + (size_t)b * D_DIM;

    float acc[E_EXP];
    #pragma unroll
    for (int e = 0; e < E_EXP; e++) acc[e] = 0.f;

    #pragma unroll
    for (int i = 0; i < 8; i++) {
        int d = i * 128 + lane * 4;
        float4 v = *(const float4*)(xr + d);
        size_t o = (size_t)b * D_DIM + d;
        *(__half2*)(g_xq + o)     = __floats2half2_rn(v.x, v.y);
        *(__half2*)(g_xq + o + 2) = __floats2half2_rn(v.z, v.w);
        float xv[4] = {v.x, v.y, v.z, v.w};
        #pragma unroll
        for (int c = 0; c < 4; c++) {
            const float4* gr = (const float4*)(gw + (size_t)(d + c) * E_EXP);
            float4 g0 = gr[0], g1 = gr[1];
            acc[0] += xv[c] * g0.x; acc[1] += xv[c] * g0.y;
            acc[2] += xv[c] * g0.z; acc[3] += xv[c] * g0.w;
            acc[4] += xv[c] * g1.x; acc[5] += xv[c] * g1.y;
            acc[6] += xv[c] * g1.z; acc[7] += xv[c] * g1.w;
        }
    }
    #pragma unroll
    for (int s = 16; s >= 1; s >>= 1)
        #pragma unroll
        for (int e = 0; e < E_EXP; e++)
            acc[e] += __shfl_xor_sync(0xffffffffu, acc[e], s);

    if (lane == 0) {
        float v0 = -1e30f, v1 = -1e30f; int i0 = 0, i1 = 0;
        #pragma unroll
        for (int ee = 0; ee < E_EXP; ee++) {
            float v = acc[ee] + gb[ee];
            if (v > v0) { v1 = v0; i1 = i0; v0 = v; i0 = ee; }
            else if (v > v1) { v1 = v; i1 = ee; }
        }
        float ex = expf(v1 - v0), inv = 1.f / (1.f + ex);
        int p0 = atomicAdd(&g_counts[i0], 1);
        int p1 = atomicAdd(&g_counts[i1], 1);
        g_eidx[b*2+0] = i0; g_epos[b*2+0] = p0; g_ew[b*2+0] = inv;
        g_eidx[b*2+1] = i1; g_epos[b*2+1] = p1; g_ew[b*2+1] = ex * inv;
    }
}

// fused scan + scatter: block 0 publishes the 8-entry scan, all 32 blocks spin
// on the flag (all blocks resident -> no deadlock), then scatter.
__global__ void scan_scatter_kernel() {
    int tid = threadIdx.x;
    if (blockIdx.x == 0 && tid == 0) {
        int acc = 0;
        #pragma unroll
        for (int e = 0; e < E_EXP; e++) { g_off[e] = acc; acc += g_counts[e]; }
        g_off[E_EXP] = acc;
        __threadfence();
        g_scan_flag = 1;
    }
    if (tid == 0) {
        while (g_scan_flag == 0) __nanosleep(64);
        __threadfence();
    }
    __syncthreads();
    int i = blockIdx.x * blockDim.x + tid;
    if (i >= NSLOT) return;
    int slot = g_off[g_eidx[i]] + g_epos[i];
    g_perm[slot] = i >> 1;
    g_rws[slot]  = g_ew[i];
}

// ---------------- conversion: fp32 -> fp16 (weights) ----------------
__global__ void convert_f16_kernel(const float* __restrict__ src,
                                   __half* __restrict__ oq) {
    size_t i = ((size_t)blockIdx.x * 256 + threadIdx.x) * 4;
    float4 v = *(const float4*)(src + i);
    *(__half2*)(oq + i)     = __floats2half2_rn(v.x, v.y);
    *(__half2*)(oq + i + 2) = __floats2half2_rn(v.z, v.w);
}

// ---------------- HMMA grouped GEMM (fp16, single pass, BK=64) — R15/R16 core ----------------
#define STAGES 3
#define STAGE_BYTES 32768
#define STG_B 16384
#define GEMM_SMEM (STAGES * STAGE_BYTES)

template <int MODE>
__global__ __launch_bounds__(256, 2)
void moe_gemm_hmma(const __half* __restrict__ Aq_base,
                   const __half* __restrict__ Wq_base,
                   const float* __restrict__ bias,
                   float* __restrict__ yout,
                   int KD, int ND, int e_base) {
    int e   = e_base + blockIdx.z;
    int cnt = g_counts[e];
    int m0  = blockIdx.y * 128;
    if (m0 >= cnt) return;
    int off = g_off[e];
    int n0  = blockIdx.x * 128;

    extern __shared__ char dsm[];
    __shared__ int s_arow[128];

    int tid  = threadIdx.x;
    int wid  = tid >> 5, lane = tid & 31;
    int wm   = (wid >> 2) * 64;
    int wn   = (wid & 3) * 32;
    int g    = lane >> 2, t4 = lane & 3;

    const __half* Wq = Wq_base + (size_t)e * KD * ND;

    if (tid < 128) {
        int r = m0 + tid;
        int src = 0;
        if (r < cnt) src = (MODE == 0) ? g_perm[off + r] : (off + r);
        s_arow[tid] = src;
    }
    __syncthreads();

    uint32_t smb = smem_u32(dsm);
    const int NC = KD >> 6;

    auto load_stage = [&](int c) {
        uint32_t sb = smb + (c % STAGES) * STAGE_BYTES;
        int k0 = c << 6;
        #pragma unroll
        for (int t = 0; t < 4; t++) {
            int cid = tid + t * 256;
            int row = cid >> 3, seg = cid & 7;
            uint32_t so = (uint32_t)(row * 128 + seg * 16) ^ (((uint32_t)row & 7u) << 4);
            cpa16(sb + so, Aq_base + (size_t)s_arow[row] * KD + k0 + seg * 8);
        }
        #pragma unroll
        for (int t = 0; t < 4; t++) {
            int cid = tid + t * 256;
            int k = cid >> 4, nseg = cid & 15;
            uint32_t so = (uint32_t)(k * 256) + ((uint32_t)(nseg * 16) ^ (((uint32_t)k & 7u) << 4));
            cpa16(sb + STG_B + so, Wq + (size_t)(k0 + k) * ND + n0 + nseg * 8);
        }
        CP_COMMIT();
    };

    load_stage(0);
    if (NC > 1) load_stage(1);

    float acc[4][4][4];
    #pragma unroll
    for (int i = 0; i < 4; i++)
        #pragma unroll
        for (int j = 0; j < 4; j++)
            #pragma unroll
            for (int q = 0; q < 4; q++) acc[i][j][q] = 0.f;

    for (int c = 0; c < NC; c++) {
        if (c + 1 < NC) cp_wait<1>(); else cp_wait<0>();
        __syncthreads();
        if (c + 2 < NC) load_stage(c + 2);

        uint32_t sb = smb + (c % STAGES) * STAGE_BYTES;

        #pragma unroll
        for (int ks = 0; ks < 4; ks++) {
            uint32_t bq[8];
            int kk = ks * 16 + (lane & 7) + ((lane >> 3) & 1) * 8;
            #pragma unroll
            for (int nf2 = 0; nf2 < 2; nf2++) {
                int noct = (wid & 3) * 4 + nf2 * 2 + (lane >> 4);
                uint32_t so = (uint32_t)(kk * 256) + ((uint32_t)(noct * 16) ^ (((uint32_t)kk & 7u) << 4));
                LDSM_X4T(bq[nf2*4+0], bq[nf2*4+1], bq[nf2*4+2], bq[nf2*4+3], sb + STG_B + so);
            }
            #pragma unroll
            for (int mf = 0; mf < 4; mf++) {
                int row = wm + mf * 16 + (lane & 7) + ((lane >> 3) & 1) * 8;
                int seg = ks * 2 + ((lane >> 4) & 1);
                uint32_t so = (uint32_t)(row * 128 + seg * 16) ^ (((uint32_t)row & 7u) << 4);
                uint32_t aq[4];
                LDSM_X4(aq[0], aq[1], aq[2], aq[3], sb + so);
                #pragma unroll
                for (int nf = 0; nf < 4; nf++)
                    mma_f16(acc[mf][nf], aq, &bq[nf*2]);
            }
        }
    }

    // ---------------- epilogue ----------------
    float bias0[4], bias1[4];
    #pragma unroll
    for (int nf = 0; nf < 4; nf++) {
        int n = n0 + wn + nf * 8 + t4 * 2;
        bias0[nf] = bias[e * ND + n];
        bias1[nf] = bias[e * ND + n + 1];
    }

    #pragma unroll
    for (int mf = 0; mf < 4; mf++) {
        #pragma unroll
        for (int half = 0; half < 2; half++) {
            int r = m0 + wm + mf * 16 + g + half * 8;
            if (r >= cnt) continue;
            if (MODE == 0) {
                size_t rb = (size_t)(off + r) * ND + n0 + wn + t4 * 2;
                #pragma unroll
                for (int nf = 0; nf < 4; nf++) {
                    float v0 = acc[mf][nf][half*2+0] + bias0[nf];
                    float v1 = acc[mf][nf][half*2+1] + bias1[nf];
                    v0 = v0 > 0.f ? v0 : 0.f;
                    v1 = v1 > 0.f ? v1 : 0.f;
                    *(__half2*)(g_hq + rb + nf * 8) = __floats2half2_rn(v0, v1);
                }
            } else {
                int tok  = g_perm[off + r];
                float rw = g_rws[off + r];
                float* orow = yout + (size_t)tok * ND + n0 + wn + t4 * 2;
                #pragma unroll
                for (int nf = 0; nf < 4; nf++) {
                    atomicAdd(&orow[nf * 8 + 0], rw * (acc[mf][nf][half*2+0] + bias0[nf]));
                    atomicAdd(&orow[nf * 8 + 1], rw * (acc[mf][nf][half*2+1] + bias1[nf]));
                }
            }
        }
    }
}

// ---------------- launch (split converts, two expert-group chains) ----------------
extern "C" void kernel_launch(void* const* d_in, const int* in_sizes, int n_in,
                              void* d_out, int out_size) {
    const float* x  = (const float*)d_in[0];
    const float* gw = (const float*)d_in[1];
    const float* gb = (const float*)d_in[2];
    const float* w1 = (const float*)d_in[3];
    const float* b1 = (const float*)d_in[4];
    const float* w2 = (const float*)d_in[5];
    const float* b2 = (const float*)d_in[6];
    float* y = (float*)d_out;

    cudaFuncSetAttribute(moe_gemm_hmma<0>, cudaFuncAttributeMaxDynamicSharedMemorySize, GEMM_SMEM);
    cudaFuncSetAttribute(moe_gemm_hmma<1>, cudaFuncAttributeMaxDynamicSharedMemorySize, GEMM_SMEM);

    __half *xq, *w1q, *w2q, *hq;
    cudaGetSymbolAddress((void**)&xq,  g_xq);
    cudaGetSymbolAddress((void**)&w1q, g_w1q);
    cudaGetSymbolAddress((void**)&w2q, g_w2q);
    cudaGetSymbolAddress((void**)&hq,  g_hq);

    const size_t W1_HALF = (size_t)4 * D_DIM * H_DIM;   // 16.7M elems
    const size_t W2_HALF = (size_t)4 * H_DIM * O_DIM;
    const int W1_BLKS = (int)(W1_HALF / 1024);
    const int W2_BLKS = (int)(W2_HALF / 1024);

    // single side stream (guard-proven pattern)
    cudaStream_t s2;
    cudaStreamCreateWithFlags(&s2, cudaStreamNonBlocking);
    cudaEvent_t evFork, evW1a, evW2a, evRoute, evB;
    cudaEventCreateWithFlags(&evFork,  cudaEventDisableTiming);
    cudaEventCreateWithFlags(&evW1a,   cudaEventDisableTiming);
    cudaEventCreateWithFlags(&evW2a,   cudaEventDisableTiming);
    cudaEventCreateWithFlags(&evRoute, cudaEventDisableTiming);
    cudaEventCreateWithFlags(&evB,     cudaEventDisableTiming);

    // y must be zero before layer-2 atomics; ordered before the fork.
    cudaMemsetAsync(y, 0, (size_t)out_size * sizeof(float));
    zero_counts_kernel<<<1, 32>>>();
    cudaEventRecord(evFork, 0);
    cudaStreamWaitEvent(s2, evFork, 0);

    // side stream: w1 group A, w1 group B, w2 group A (group-B's w2 comes later)
    convert_f16_kernel<<<W1_BLKS, 256, 0, s2>>>(w1, w1q);                       // experts 0-3
    cudaEventRecord(evW1a, s2);
    convert_f16_kernel<<<W1_BLKS, 256, 0, s2>>>(w1 + W1_HALF, w1q + W1_HALF);   // experts 4-7
    convert_f16_kernel<<<W2_BLKS, 256, 0, s2>>>(w2, w2q);                       // experts 0-3
    cudaEventRecord(evW2a, s2);

    // main stream: routing chain (x convert fused in router; scan fused in scatter)
    router_kernel<<<B_TOK / 8, 256>>>(x, gw, gb);
    scan_scatter_kernel<<<(NSLOT + 255) / 256, 256>>>();
    cudaEventRecord(evRoute, 0);

    // group A (experts 0-3) on stream 0
    cudaStreamWaitEvent(0, evW1a, 0);
    moe_gemm_hmma<0><<<dim3(H_DIM / 128, 32, 4), 256, GEMM_SMEM>>>(
        xq, w1q, b1, nullptr, D_DIM, H_DIM, 0);
    cudaStreamWaitEvent(0, evW2a, 0);
    moe_gemm_hmma<1><<<dim3(O_DIM / 128, 32, 4), 256, GEMM_SMEM>>>(
        hq, w2q, b2, y, H_DIM, O_DIM, 0);

    // group B (experts 4-7) on s2: G1B, then w2 group-B convert, then G2B
    cudaStreamWaitEvent(s2, evRoute, 0);
    moe_gemm_hmma<0><<<dim3(H_DIM / 128, 32, 4), 256, GEMM_SMEM, s2>>>(
        xq, w1q, b1, nullptr, D_DIM, H_DIM, 4);
    convert_f16_kernel<<<W2_BLKS, 256, 0, s2>>>(w2 + W2_HALF, w2q + W2_HALF);   // experts 4-7
    moe_gemm_hmma<1><<<dim3(O_DIM / 128, 32, 4), 256, GEMM_SMEM, s2>>>(
        hq, w2q, b2, y, H_DIM, O_DIM, 4);
    cudaEventRecord(evB, s2);

    // join side stream back into the capture-origin stream
    cudaStreamWaitEvent(0, evB, 0);
    // stream/events intentionally not destroyed (two invocations only:
    // correctness run + graph capture).
}